// round 7
// baseline (speedup 1.0000x reference)
#include <cuda_runtime.h>
#include <math.h>

#define NN 100000
#define EE 3200000
#define K_SEL 11111
#define LN_EPS 1e-5f

// ---------------- scratch (device globals; no allocation) ----------------
__device__ __align__(16) int    g_src[EE];
__device__ __align__(16) int    g_dst[EE];
__device__ __align__(16) float  g_nw[EE];      // |attr| then norm (in place)
__device__ __align__(16) float  g_deg[NN];     // deg then dinv (in place)
__device__ __align__(16) float  g_sA[NN];
__device__ __align__(16) float  g_sB[NN];
__device__ __align__(16) float  g_f0[NN * 8];
__device__ __align__(16) float  g_f1[NN * 8];
__device__ __align__(16) float  g_acc[NN * 8];
__device__ __align__(16) float  g_h[NN];
__device__ double   g_red[2];                  // sum, sumsq
__device__ unsigned g_hist[256];
__device__ unsigned g_prefix;
__device__ unsigned g_krem;
__device__ float    g_thresh;
__device__ unsigned g_cnt[2];                  // n_gt, n_tie
__device__ int      g_is64;
__device__ unsigned char g_tiemark[NN];

// ---------------- helpers ----------------
__device__ __forceinline__ float* sel_s(int s) { return (s == 1) ? g_sA : g_sB; }

__device__ __forceinline__ void red_add_v4(float* p, float4 v) {
    asm volatile("red.global.add.v4.f32 [%0], {%1, %2, %3, %4};"
                 :: "l"(p), "f"(v.x), "f"(v.y), "f"(v.z), "f"(v.w) : "memory");
}

__device__ __forceinline__ unsigned desc_key(float x) {
    unsigned u = __float_as_uint(x);
    unsigned asc = (u & 0x80000000u) ? ~u : (u | 0x80000000u); // ascending order key
    return ~asc;                                               // descending order key
}

// ---------------- kernels ----------------

// Detect whether edge_index buffer is int64 or int32.
// If int64 (values < 2^31), the high 32-bit word of every entry is 0.
// If int32, odd words are random edge indices — virtually surely nonzero somewhere.
__global__ void k_detect(const int* __restrict__ ei32) {
    __shared__ int bad;
    if (threadIdx.x == 0) bad = 0;
    __syncthreads();
    for (int i = threadIdx.x; i < 512; i += blockDim.x)
        if (ei32[2 * i + 1] != 0) bad = 1;
    __syncthreads();
    if (threadIdx.x == 0) g_is64 = bad ? 0 : 1;
}

__global__ void k_init() {
    int i = blockIdx.x * blockDim.x + threadIdx.x;
    if (i < NN) g_deg[i] = 0.f;
    if (i < 256) g_hist[i] = 0u;
    if (i == 0) {
        g_red[0] = 0.0; g_red[1] = 0.0;
        g_prefix = 0u; g_krem = (unsigned)K_SEL;
        g_cnt[0] = 0u; g_cnt[1] = 0u;
    }
}

__global__ void k_edge_prep(const void* __restrict__ eiv,
                            const float* __restrict__ attr) {
    int e = blockIdx.x * blockDim.x + threadIdx.x;
    if (e >= EE) return;
    int s, d;
    if (g_is64) {
        const long long* ei = (const long long*)eiv;
        s = (int)ei[e];
        d = (int)ei[EE + e];
    } else {
        const int* ei = (const int*)eiv;
        s = ei[e];
        d = ei[EE + e];
    }
    // defensive clamp: never let a bad index crash the run
    s = min(max(s, 0), NN - 1);
    d = min(max(d, 0), NN - 1);
    float w = fabsf(attr[e]);
    g_src[e] = s; g_dst[e] = d; g_nw[e] = w;
    atomicAdd(&g_deg[d], w);
}

__global__ void k_dinv() {
    int i = blockIdx.x * blockDim.x + threadIdx.x;
    if (i >= NN) return;
    float dg = g_deg[i];
    g_deg[i] = (dg > 0.f) ? rsqrtf(dg) : 0.f;
}

__global__ void k_norm() {
    int e = blockIdx.x * blockDim.x + threadIdx.x;
    if (e >= EE) return;
    g_nw[e] = g_deg[g_src[e]] * g_nw[e] * g_deg[g_dst[e]];
}

// scalar scatter: d[dst] += norm * s[src]
__global__ void k_scat1(const float* __restrict__ xext, int ssel, int dsel) {
    int e = blockIdx.x * blockDim.x + threadIdx.x;
    if (e >= EE) return;
    const float* s = (ssel == 0) ? xext : sel_s(ssel);
    float* d = sel_s(dsel);
    atomicAdd(&d[g_dst[e]], g_nw[e] * __ldg(&s[g_src[e]]));
}

// 8-channel scatter: d[dst,:] += norm * s[src,:]
__global__ void k_scat8(int dir) {  // dir 0: f0->f1, 1: f1->f0
    int e = blockIdx.x * blockDim.x + threadIdx.x;
    if (e >= EE) return;
    const float* s = dir ? g_f1 : g_f0;
    float* d = dir ? g_f0 : g_f1;
    int ss = g_src[e], dd = g_dst[e];
    float nrm = g_nw[e];
    const float4* sp = reinterpret_cast<const float4*>(s + (size_t)ss * 8);
    float4 a = __ldg(sp), b = __ldg(sp + 1);
    a.x *= nrm; a.y *= nrm; a.z *= nrm; a.w *= nrm;
    b.x *= nrm; b.y *= nrm; b.z *= nrm; b.w *= nrm;
    float* dp = d + (size_t)dd * 8;
    red_add_v4(dp, a);
    red_add_v4(dp + 4, b);
}

// layer1: acc = x*W1[0]; zero sA
__global__ void k_l1_init(const float* __restrict__ x, const float* __restrict__ W1) {
    int n = blockIdx.x * blockDim.x + threadIdx.x;
    if (n >= NN) return;
    float xv = x[n];
    #pragma unroll
    for (int j = 0; j < 8; j++) g_acc[n * 8 + j] = xv * __ldg(&W1[j]);
    g_sA[n] = 0.f;
}

__global__ void k_l1_acc(int ssel, int hop, int zsel, const float* __restrict__ W1) {
    int n = blockIdx.x * blockDim.x + threadIdx.x;
    if (n >= NN) return;
    float sv = sel_s(ssel)[n];
    #pragma unroll
    for (int j = 0; j < 8; j++) g_acc[n * 8 + j] += sv * __ldg(&W1[hop * 8 + j]);
    sel_s(zsel)[n] = 0.f;
}

// layer1 finish + start of layer2: f0 = relu(acc + s*W1[3] + b1); acc = f0@W2[0]; zero f1
__global__ void k_l1_final(int ssel, const float* __restrict__ W1,
                           const float* __restrict__ b1, const float* __restrict__ W2) {
    int n = blockIdx.x * blockDim.x + threadIdx.x;
    if (n >= NN) return;
    float sv = sel_s(ssel)[n];
    float v[8];
    #pragma unroll
    for (int j = 0; j < 8; j++) {
        float a = g_acc[n * 8 + j] + sv * __ldg(&W1[24 + j]) + __ldg(&b1[j]);
        v[j] = fmaxf(a, 0.f);
        g_f0[n * 8 + j] = v[j];
    }
    #pragma unroll
    for (int c = 0; c < 8; c++) {
        float a = 0.f;
        #pragma unroll
        for (int r = 0; r < 8; r++) a += v[r] * __ldg(&W2[r * 8 + c]);
        g_acc[n * 8 + c] = a;
    }
    float4 z = make_float4(0.f, 0.f, 0.f, 0.f);
    reinterpret_cast<float4*>(g_f1 + (size_t)n * 8)[0] = z;
    reinterpret_cast<float4*>(g_f1 + (size_t)n * 8)[1] = z;
}

// layer2 hop accumulate: acc += hop @ W2[hopi]; zero the other buffer
__global__ void k_l2_acc(int dir, int hopi, const float* __restrict__ W2) {
    int n = blockIdx.x * blockDim.x + threadIdx.x;
    if (n >= NN) return;
    const float* hop = dir ? g_f1 : g_f0;
    float* zb = dir ? g_f0 : g_f1;
    float hv[8];
    #pragma unroll
    for (int r = 0; r < 8; r++) hv[r] = hop[n * 8 + r];
    const float* w = W2 + hopi * 64;
    #pragma unroll
    for (int c = 0; c < 8; c++) {
        float a = g_acc[n * 8 + c];
        #pragma unroll
        for (int r = 0; r < 8; r++) a += hv[r] * __ldg(&w[r * 8 + c]);
        g_acc[n * 8 + c] = a;
    }
    float4 z = make_float4(0.f, 0.f, 0.f, 0.f);
    reinterpret_cast<float4*>(zb + (size_t)n * 8)[0] = z;
    reinterpret_cast<float4*>(zb + (size_t)n * 8)[1] = z;
}

// layer2 finish + start of layer3: v = relu(acc + f1@W2[3] + b2); f0 = v; g_h = v@W3[0]; zero f1
__global__ void k_l2_final(const float* __restrict__ W2, const float* __restrict__ b2,
                           const float* __restrict__ W3) {
    int n = blockIdx.x * blockDim.x + threadIdx.x;
    if (n >= NN) return;
    float hv[8];
    #pragma unroll
    for (int r = 0; r < 8; r++) hv[r] = g_f1[n * 8 + r];
    float v[8];
    #pragma unroll
    for (int c = 0; c < 8; c++) {
        float a = g_acc[n * 8 + c] + __ldg(&b2[c]);
        #pragma unroll
        for (int r = 0; r < 8; r++) a += hv[r] * __ldg(&W2[192 + r * 8 + c]);
        v[c] = fmaxf(a, 0.f);
        g_f0[n * 8 + c] = v[c];
    }
    float hs = 0.f;
    #pragma unroll
    for (int r = 0; r < 8; r++) hs += v[r] * __ldg(&W3[r]);
    g_h[n] = hs;
    float4 z = make_float4(0.f, 0.f, 0.f, 0.f);
    reinterpret_cast<float4*>(g_f1 + (size_t)n * 8)[0] = z;
    reinterpret_cast<float4*>(g_f1 + (size_t)n * 8)[1] = z;
}

__global__ void k_l3_acc(int dir, int hopi, const float* __restrict__ W3) {
    int n = blockIdx.x * blockDim.x + threadIdx.x;
    if (n >= NN) return;
    const float* hop = dir ? g_f1 : g_f0;
    float* zb = dir ? g_f0 : g_f1;
    float a = g_h[n];
    #pragma unroll
    for (int r = 0; r < 8; r++) a += hop[n * 8 + r] * __ldg(&W3[hopi * 8 + r]);
    g_h[n] = a;
    float4 z = make_float4(0.f, 0.f, 0.f, 0.f);
    reinterpret_cast<float4*>(zb + (size_t)n * 8)[0] = z;
    reinterpret_cast<float4*>(zb + (size_t)n * 8)[1] = z;
}

// layer3 finish: g_h = relu(g_h + f1@W3[3] + b3); reduce sum/sumsq
__global__ void k_l3_final(const float* __restrict__ W3, const float* __restrict__ b3) {
    int n = blockIdx.x * blockDim.x + threadIdx.x;
    float v = 0.f;
    if (n < NN) {
        float a = g_h[n] + __ldg(b3);
        #pragma unroll
        for (int r = 0; r < 8; r++) a += g_f1[n * 8 + r] * __ldg(&W3[24 + r]);
        v = fmaxf(a, 0.f);
        g_h[n] = v;
    }
    __shared__ double ss[256], sq[256];
    ss[threadIdx.x] = (double)v;
    sq[threadIdx.x] = (double)v * (double)v;
    __syncthreads();
    for (int off = 128; off > 0; off >>= 1) {
        if (threadIdx.x < off) {
            ss[threadIdx.x] += ss[threadIdx.x + off];
            sq[threadIdx.x] += sq[threadIdx.x + off];
        }
        __syncthreads();
    }
    if (threadIdx.x == 0) {
        atomicAdd(&g_red[0], ss[0]);
        atomicAdd(&g_red[1], sq[0]);
    }
}

// standardize; write out[:,0]
__global__ void k_normout(float* __restrict__ out) {
    int n = blockIdx.x * blockDim.x + threadIdx.x;
    if (n >= NN) return;
    double mu = g_red[0] / (double)NN;
    double var = g_red[1] / (double)NN - mu * mu;
    float muf = (float)mu;
    float inv = rsqrtf((float)var + LN_EPS);
    float hn = (g_h[n] - muf) * inv;
    g_h[n] = hn;
    out[2 * n] = hn;
}

// radix select (k-th largest): histogram pass over byte b (3..0)
__global__ void k_hist(int b) {
    __shared__ unsigned sh[256];
    for (int i = threadIdx.x; i < 256; i += blockDim.x) sh[i] = 0u;
    __syncthreads();
    unsigned prefix = g_prefix;
    unsigned maskHigh = (b == 3) ? 0u : (0xFFFFFFFFu << ((b + 1) * 8));
    for (int i = blockIdx.x * blockDim.x + threadIdx.x; i < NN; i += gridDim.x * blockDim.x) {
        unsigned d = desc_key(g_h[i]);
        if (((d ^ prefix) & maskHigh) == 0u)
            atomicAdd(&sh[(d >> (b * 8)) & 0xFFu], 1u);
    }
    __syncthreads();
    for (int i = threadIdx.x; i < 256; i += blockDim.x)
        if (sh[i]) atomicAdd(&g_hist[i], sh[i]);
}

__global__ void k_pick(int b) {  // <<<1,256>>>
    __shared__ unsigned sh[256];
    int t = threadIdx.x;
    sh[t] = g_hist[t];
    g_hist[t] = 0u;  // ready for next pass
    __syncthreads();
    if (t == 0) {
        unsigned krem = g_krem, cum = 0u;
        int j = 0;
        for (; j < 256; j++) {
            if (cum + sh[j] >= krem) break;
            cum += sh[j];
        }
        if (j > 255) j = 255;  // defensive: never shift garbage
        g_krem = krem - cum;
        unsigned prefix = g_prefix | ((unsigned)j << (b * 8));
        g_prefix = prefix;
        if (b == 0) {
            unsigned asc = ~prefix;
            unsigned u = (asc & 0x80000000u) ? (asc ^ 0x80000000u) : ~asc;
            g_thresh = __uint_as_float(u);
        }
    }
}

__global__ void k_count() {
    int i = blockIdx.x * blockDim.x + threadIdx.x;
    if (i >= NN) return;
    float x = g_h[i], th = g_thresh;
    if (x > th) atomicAdd(&g_cnt[0], 1u);
    else if (x == th) atomicAdd(&g_cnt[1], 1u);
}

// rare path: stable (index-ordered) selection among boundary ties. <<<1,1024>>>
__global__ void k_tiemark() {
    int r = K_SEL - (int)g_cnt[0];
    int t = (int)g_cnt[1];
    if (t == r) return;  // uniform: no tie ambiguity
    float th = g_thresh;
    __shared__ unsigned warpsum[32];
    __shared__ unsigned woff[32];
    __shared__ unsigned s_running;
    if (threadIdx.x == 0) s_running = 0u;
    __syncthreads();
    int lane = threadIdx.x & 31, w = threadIdx.x >> 5;
    for (int base = 0; base < NN; base += (int)blockDim.x) {
        int i = base + threadIdx.x;
        bool f = (i < NN) && (g_h[i] == th);
        unsigned bal = __ballot_sync(0xFFFFFFFFu, f);
        unsigned pre = __popc(bal & ((1u << lane) - 1u));
        if (lane == 0) warpsum[w] = __popc(bal);
        __syncthreads();
        if (threadIdx.x == 0) {
            unsigned run = s_running;
            for (int j = 0; j < 32; j++) { woff[j] = run; run += warpsum[j]; }
            s_running = run;
        }
        __syncthreads();
        if (f) {
            unsigned rank = woff[w] + pre;
            g_tiemark[i] = (rank < (unsigned)r) ? 1 : 0;
        }
        __syncthreads();
    }
}

__global__ void k_final(float* __restrict__ out) {
    int i = blockIdx.x * blockDim.x + threadIdx.x;
    if (i >= NN) return;
    float hn = g_h[i], th = g_thresh;
    int r = K_SEL - (int)g_cnt[0];
    int nt = (int)g_cnt[1];
    bool inset;
    if (hn > th) inset = true;
    else if (hn == th) inset = (nt == r) ? true : (g_tiemark[i] != 0);
    else inset = false;
    float z = hn - fabsf(th) + (inset ? 0.1f : -0.1f);
    out[2 * i + 1] = 1.f / (1.f + expf(-z));
}

// ---------------- launch ----------------
extern "C" void kernel_launch(void* const* d_in, const int* in_sizes, int n_in,
                              void* d_out, int out_size) {
    const float* x    = (const float*)d_in[0];
    const float* attr = (const float*)d_in[1];
    const float* W1   = (const float*)d_in[2];
    const float* b1   = (const float*)d_in[3];
    const float* W2   = (const float*)d_in[4];
    const float* b2   = (const float*)d_in[5];
    const float* W3   = (const float*)d_in[6];
    const float* b3   = (const float*)d_in[7];
    const void*  ei   = d_in[8];
    float* out = (float*)d_out;

    const int TB = 256;
    const int gN = (NN + TB - 1) / TB;
    const int gE = (EE + TB - 1) / TB;

    k_detect<<<1, 256>>>((const int*)ei);
    k_init<<<gN, TB>>>();
    k_edge_prep<<<gE, TB>>>(ei, attr);
    k_dinv<<<gN, TB>>>();
    k_norm<<<gE, TB>>>();

    // ---- layer 1 (1 -> 8) ----
    k_l1_init<<<gN, TB>>>(x, W1);          // acc = x*W1[0], zero sA
    k_scat1<<<gE, TB>>>(x, 0, 1);          // x -> sA
    k_l1_acc<<<gN, TB>>>(1, 1, 2, W1);     // acc += sA*W1[1], zero sB
    k_scat1<<<gE, TB>>>(nullptr, 1, 2);    // sA -> sB
    k_l1_acc<<<gN, TB>>>(2, 2, 1, W1);     // acc += sB*W1[2], zero sA
    k_scat1<<<gE, TB>>>(nullptr, 2, 1);    // sB -> sA
    k_l1_final<<<gN, TB>>>(1, W1, b1, W2); // f0 = relu(...); acc = f0@W2[0]; zero f1

    // ---- layer 2 (8 -> 8) ----
    k_scat8<<<gE, TB>>>(0);                // f0 -> f1
    k_l2_acc<<<gN, TB>>>(1, 1, W2);        // acc += f1@W2[1], zero f0
    k_scat8<<<gE, TB>>>(1);                // f1 -> f0
    k_l2_acc<<<gN, TB>>>(0, 2, W2);        // acc += f0@W2[2], zero f1
    k_scat8<<<gE, TB>>>(0);                // f0 -> f1
    k_l2_final<<<gN, TB>>>(W2, b2, W3);    // f0 = relu(...); g_h = f0@W3[0]; zero f1

    // ---- layer 3 (8 -> 1) ----
    k_scat8<<<gE, TB>>>(0);                // f0 -> f1
    k_l3_acc<<<gN, TB>>>(1, 1, W3);        // g_h += f1@W3[1], zero f0
    k_scat8<<<gE, TB>>>(1);                // f1 -> f0
    k_l3_acc<<<gN, TB>>>(0, 2, W3);        // g_h += f0@W3[2], zero f1
    k_scat8<<<gE, TB>>>(0);                // f0 -> f1
    k_l3_final<<<gN, TB>>>(W3, b3);        // g_h = relu(...); reduce

    // ---- standardize + output col 0 ----
    k_normout<<<gN, TB>>>(out);

    // ---- radix select k-th largest ----
    for (int b = 3; b >= 0; b--) {
        k_hist<<<256, 256>>>(b);
        k_pick<<<1, 256>>>(b);
    }
    k_count<<<gN, TB>>>();
    k_tiemark<<<1, 1024>>>();
    k_final<<<gN, TB>>>(out);
}